// round 15
// baseline (speedup 1.0000x reference)
#include <cuda_runtime.h>
#include <cuda_fp16.h>
#include <cstdint>

// ============================================================================
// relu(x @ W^T + b): M=131072, N=256, K=256, fp32.  Base sm_103 target.
// R12: fp16 m16n8k16 (R11) + occupancy 2x: CTA 128x128 with 256 threads,
// 8 warps, warp tile 32x64 (acc=64 regs) -> 2 CTAs/SM = 16 warps/SM.
// KC=32, 3-stage cp.async, grid(2,1024) for L2 x reuse.
// B: W pre-converted fp16 -> cp.async -> ldmatrix -> MMA (zero cvt).
// A: fp32 smem -> ld.shared.v2 -> cvt.rn.f16x2 pack in-loop.
// ============================================================================

static constexpr int DK = 256;
static constexpr int DN = 256;
static constexpr int BM = 128;
static constexpr int BN = 128;
static constexpr int KC = 32;
static constexpr int THREADS = 256;
static constexpr int NSTAGE = 3;

static constexpr int A_BYTES = BM * KC * 4;   // 16384 (fp32)
static constexpr int B_BYTES = BN * 128;      // 16384 (fp16, rows padded to 128B)
static constexpr int STAGE_BYTES = A_BYTES + B_BYTES;   // 32768
static constexpr int SMEM_DYN = NSTAGE * STAGE_BYTES;   // 98304

__device__ __half W_h[DN * DK];               // 128KB fp16 weight scratch

// ---------------------------------------------------------------------------
__device__ __forceinline__ uint32_t smem_u32(const void* p) {
    uint32_t a;
    asm("{ .reg .u64 t; cvta.to.shared.u64 t, %1; cvt.u32.u64 %0, t; }" : "=r"(a) : "l"(p));
    return a;
}
__device__ __forceinline__ void cp_async16(uint32_t dst, const void* src) {
    asm volatile("cp.async.cg.shared.global [%0], [%1], 16;" :: "r"(dst), "l"(src));
}
__device__ __forceinline__ void ldsm_x4(uint32_t* d, uint32_t addr) {
    asm volatile("ldmatrix.sync.aligned.m8n8.x4.shared.b16 {%0,%1,%2,%3}, [%4];"
                 : "=r"(d[0]), "=r"(d[1]), "=r"(d[2]), "=r"(d[3]) : "r"(addr));
}
__device__ __forceinline__ uint32_t pack_f16(float hi, float lo) {
    uint32_t d;
    asm("cvt.rn.f16x2.f32 %0, %1, %2;" : "=r"(d) : "f"(hi), "f"(lo));
    return d;
}
__device__ __forceinline__ float2 lds64(uint32_t addr) {
    float2 v;
    asm volatile("ld.shared.v2.f32 {%0, %1}, [%2];" : "=f"(v.x), "=f"(v.y) : "r"(addr));
    return v;
}
__device__ __forceinline__ void mma_f16(float* d, const uint32_t* a,
                                        uint32_t b0, uint32_t b1) {
    asm volatile(
        "mma.sync.aligned.m16n8k16.row.col.f32.f16.f16.f32 "
        "{%0,%1,%2,%3}, {%4,%5,%6,%7}, {%8,%9}, {%0,%1,%2,%3};"
        : "+f"(d[0]), "+f"(d[1]), "+f"(d[2]), "+f"(d[3])
        : "r"(a[0]), "r"(a[1]), "r"(a[2]), "r"(a[3]), "r"(b0), "r"(b1));
}
__device__ __forceinline__ uint32_t swz(int row, int seg) {
    return (uint32_t)row * 128u + (uint32_t)((seg * 16) ^ ((row & 7) * 16));
}

// ---------------------------------------------------------------------------
// pre-pass: W (fp32) -> fp16
__global__ void convert_W_kernel(const float* __restrict__ W) {
    int i = blockIdx.x * 256 + threadIdx.x;     // 16384 float4
    float4 v = reinterpret_cast<const float4*>(W)[i];
    uint2 o;
    o.x = pack_f16(v.y, v.x);
    o.y = pack_f16(v.w, v.z);
    reinterpret_cast<uint2*>(W_h)[i] = o;
}

// ---------------------------------------------------------------------------
__global__ __launch_bounds__(THREADS, 2)
void gemm_relu_f16_kernel(const float* __restrict__ x,
                          const float* __restrict__ bias, float* __restrict__ out) {
    extern __shared__ __align__(1024) char smem_raw[];
    const uint32_t base = smem_u32(smem_raw);

    const int tid = threadIdx.x;
    const int wid = tid >> 5;      // 0..7
    const int lid = tid & 31;
    const int g   = lid >> 2;      // 0..7
    const int t   = lid & 3;       // 0..3
    const int wm  = wid & 3;       // 4 x 32-row m-tiles
    const int wn  = wid >> 2;      // 2 x 64-col n-tiles
    const int n0  = blockIdx.x * BN;      // N fastest-varying -> L2 x reuse
    const int m0  = blockIdx.y * BM;
    const __half* Wp = W_h + (size_t)n0 * DK;

    // ldmatrix lane role for B
    const int mx = lid >> 3;       // 0..3
    const int r  = lid & 7;
    const uint32_t xr = (uint32_t)(r * 16);
    uint32_t b_row[4];
    #pragma unroll
    for (int ntp = 0; ntp < 4; ntp++)
        b_row[ntp] = (uint32_t)(wn * 64 + ntp * 16 + (mx & 1) * 8 + r) * 128u;
    const uint32_t b_sel = (uint32_t)((mx >> 1) * 16);

    // A fragment LDS base rows (warp tile 32 rows: mt 0..1)
    uint32_t aL_row[2], aH_row[2];
    #pragma unroll
    for (int mt = 0; mt < 2; mt++) {
        aL_row[mt] = (uint32_t)(wm * 32 + mt * 16 + g) * 128u;
        aH_row[mt] = (uint32_t)(wm * 32 + mt * 16 + g + 8) * 128u;
    }
    const uint32_t xg = (uint32_t)(g * 16);

    // load roles (256 threads)
    const int lrowA = tid >> 3;      // 0..31
    const int lsegA = tid & 7;       // 0..7
    const int lrowB = tid >> 2;      // 0..63
    const int lsegB = tid & 3;       // 0..3

    // ---- prologue: stage chunks 0,1 into stages 0,1
    #pragma unroll
    for (int pc = 0; pc < 2; pc++) {
        const uint32_t S = base + (uint32_t)pc * STAGE_BYTES;
        const int k0 = pc * KC;
        #pragma unroll
        for (int i = 0; i < 4; i++) {
            int row = i * 32 + lrowA;
            cp_async16(S + swz(row, lsegA), x + (size_t)(m0 + row) * DK + k0 + lsegA * 4);
        }
        #pragma unroll
        for (int i = 0; i < 2; i++) {
            int row = i * 64 + lrowB;
            cp_async16(S + A_BYTES + swz(row, lsegB),
                       Wp + (size_t)row * DK + k0 + lsegB * 8);
        }
        asm volatile("cp.async.commit_group;" ::: "memory");
    }

    float acc[2][8][4];              // warp tile 32x64
    #pragma unroll
    for (int mt = 0; mt < 2; mt++)
        #pragma unroll
        for (int nt = 0; nt < 8; nt++)
            #pragma unroll
            for (int j = 0; j < 4; j++) acc[mt][nt][j] = 0.0f;

    int stage = 0, dst = 2;
    #pragma unroll 1
    for (int kc = 0; kc < 8; kc++) {
        if (kc < 7)
            asm volatile("cp.async.wait_group 1;" ::: "memory");
        else
            asm volatile("cp.async.wait_group 0;" ::: "memory");  // drain last chunk
        __syncthreads();

        const uint32_t As = base + (uint32_t)stage * STAGE_BYTES;
        const uint32_t Bs = As + A_BYTES;

        if (kc < 6) {
            const uint32_t Ad = base + (uint32_t)dst * STAGE_BYTES;
            const int k2 = (kc + 2) * KC;
            #pragma unroll
            for (int i = 0; i < 4; i++) {
                int row = i * 32 + lrowA;
                cp_async16(Ad + swz(row, lsegA),
                           x + (size_t)(m0 + row) * DK + k2 + lsegA * 4);
            }
            #pragma unroll
            for (int i = 0; i < 2; i++) {
                int row = i * 64 + lrowB;
                cp_async16(Ad + A_BYTES + swz(row, lsegB),
                           Wp + (size_t)row * DK + k2 + lsegB * 8);
            }
            asm volatile("cp.async.commit_group;" ::: "memory");
        }

        #pragma unroll
        for (int kk = 0; kk < 2; kk++) {      // 2 x k16 per chunk
            // ---- B fragments: 4 n16 tiles, direct fp16 ldmatrix
            uint32_t bb[4][4];
            const uint32_t bcol = ((uint32_t)(kk * 32) + b_sel) ^ xr;
            #pragma unroll
            for (int ntp = 0; ntp < 4; ntp++)
                ldsm_x4(bb[ntp], Bs + b_row[ntp] + bcol);

            // ---- A fragments: fp32 LDS.64 pairs -> fp16x2 pack
            uint32_t a[2][4];
            const uint32_t cLo = ((uint32_t)(kk * 64 + t * 8));
            #pragma unroll
            for (int mt = 0; mt < 2; mt++) {
                float2 v00 = lds64(As + aL_row[mt] + (cLo ^ xg));
                float2 v01 = lds64(As + aH_row[mt] + (cLo ^ xg));
                float2 v10 = lds64(As + aL_row[mt] + ((cLo + 32) ^ xg));
                float2 v11 = lds64(As + aH_row[mt] + ((cLo + 32) ^ xg));
                a[mt][0] = pack_f16(v00.y, v00.x);
                a[mt][1] = pack_f16(v01.y, v01.x);
                a[mt][2] = pack_f16(v10.y, v10.x);
                a[mt][3] = pack_f16(v11.y, v11.x);
            }

            // ---- 16 MMAs (m16n8k16)
            #pragma unroll
            for (int mt = 0; mt < 2; mt++) {
                #pragma unroll
                for (int ntp = 0; ntp < 4; ntp++) {
                    mma_f16(acc[mt][2 * ntp],     a[mt], bb[ntp][0], bb[ntp][2]);
                    mma_f16(acc[mt][2 * ntp + 1], a[mt], bb[ntp][1], bb[ntp][3]);
                }
            }
        }

        stage = (stage == NSTAGE - 1) ? 0 : stage + 1;
        dst   = (dst == NSTAGE - 1) ? 0 : dst + 1;
    }

    // ---- epilogue: bias + relu, float2 stores
    const int m_base = m0 + wm * 32;
    const int n_base = n0 + wn * 64;
    #pragma unroll
    for (int nt = 0; nt < 8; nt++) {
        const int col = n_base + nt * 8 + 2 * t;
        const float2 bv = *reinterpret_cast<const float2*>(bias + col);
        #pragma unroll
        for (int mt = 0; mt < 2; mt++) {
            const int row0 = m_base + mt * 16 + g;
            float2 v0;
            v0.x = fmaxf(acc[mt][nt][0] + bv.x, 0.0f);
            v0.y = fmaxf(acc[mt][nt][1] + bv.y, 0.0f);
            *reinterpret_cast<float2*>(out + (size_t)row0 * DN + col) = v0;
            float2 v1;
            v1.x = fmaxf(acc[mt][nt][2] + bv.x, 0.0f);
            v1.y = fmaxf(acc[mt][nt][3] + bv.y, 0.0f);
            *reinterpret_cast<float2*>(out + (size_t)(row0 + 8) * DN + col) = v1;
        }
    }
}

// ---------------------------------------------------------------------------
extern "C" void kernel_launch(void* const* d_in, const int* in_sizes, int n_in,
                              void* d_out, int out_size) {
    const float* x = (const float*)d_in[0];
    const float* W = (const float*)d_in[1];
    const float* b = (const float*)d_in[2];
    float* out = (float*)d_out;

    int Brows = in_sizes[0] / DK;     // 131072
    dim3 grid(DN / BN, Brows / BM);   // (2, 1024)

    convert_W_kernel<<<DN * DK / 4 / 256, 256>>>(W);   // 64 blocks

    cudaFuncSetAttribute(gemm_relu_f16_kernel,
                         cudaFuncAttributeMaxDynamicSharedMemorySize, SMEM_DYN);
    gemm_relu_f16_kernel<<<grid, THREADS, SMEM_DYN>>>(x, b, out);
}